// round 15
// baseline (speedup 1.0000x reference)
#include <cuda_runtime.h>
#include <cuda_bf16.h>
#include <math.h>
#include <stdint.h>

#define NNODES 160000
#define NEDGES 2560000
#define GG 8
#define EPSV 1e-5f

// ---------------- scratch (device globals; no allocation allowed) ----------
__device__ int   g_is64;
__device__ int   g_ei[2 * NEDGES];
__device__ int   g_deg[NNODES];
__device__ float g_dis[NNODES];
__device__ int   g_rowptr[NNODES + 1];
__device__ int   g_fill[NNODES];
__device__ __align__(16) int2 g_cw[NEDGES];                     // packed (col, w)

__device__ __align__(16) float g_tx0p[NNODES * 24];             // layer0 Tx padded [N][6][4]
__device__ __align__(16) float g_h1[(size_t)NNODES * 128];      // layer1 input
__device__ __align__(16) float g_hw[(size_t)NNODES * 384];      // H@W products (6 slices)
__device__ __align__(16) float g_b0[(size_t)NNODES * 64];       // Clenshaw b (rotating)
__device__ __align__(16) float g_b1[(size_t)NNODES * 64];
__device__ __align__(16) float g_b2[(size_t)NNODES * 64];
__device__ __align__(16) float g_h2[(size_t)NNODES * 64];       // layer2 input
__device__ __align__(16) float g_h3[NNODES * 32];               // head input
__device__ float g_partial[625 * 2048];

// pre-split bf16 planes (pair-packed along K): A (activations) and W
__device__ __align__(16) uint32_t g_ah[(size_t)NNODES * 64];
__device__ __align__(16) uint32_t g_al[(size_t)NNODES * 64];
__device__ __align__(16) uint32_t g_wh[6 * 64 * 64];
__device__ __align__(16) uint32_t g_wl[6 * 64 * 64];

template <int B>
__device__ __forceinline__ float* buf() {
    if constexpr (B == 1) return g_h1;
    else if constexpr (B == 2) return g_hw;
    else if constexpr (B == 3) return g_b0;
    else if constexpr (B == 4) return g_b1;
    else if constexpr (B == 5) return g_b2;
    else if constexpr (B == 6) return g_h2;
    else return g_h3;
}

__device__ __forceinline__ float* bufsel(int b) {
    switch (b) {
        case 2: return g_hw;
        case 3: return g_b0;
        case 4: return g_b1;
        case 5: return g_b2;
        case 6: return g_h2;
        default: return g_h3;
    }
}

__device__ __forceinline__ void split_pack(float v0, float v1,
                                           uint32_t& hi, uint32_t& lo) {
    __nv_bfloat162 h = __floats2bfloat162_rn(v0, v1);
    float r0 = v0 - __low2float(h);
    float r1 = v1 - __high2float(h);
    __nv_bfloat162 l = __floats2bfloat162_rn(r0, r1);
    hi = *(uint32_t*)&h;
    lo = *(uint32_t*)&l;
}

// ---------------- edge dtype detection (parallel) ----------------------------
__global__ void k_detect(const void* ei_raw, int n_elems) {
    __shared__ int bad;
    if (threadIdx.x == 0) bad = 0;
    __syncthreads();
    const long long* p = (const long long*)ei_raw;
    int nw = n_elems / 2;
    if (nw > 2048) nw = 2048;
    for (int j = threadIdx.x; j < nw; j += 256) {
        long long v = p[j];
        if (v < 0 || v >= NNODES) bad = 1;
    }
    __syncthreads();
    if (threadIdx.x == 0) g_is64 = bad ? 0 : 1;
}

__global__ void k_convert(const void* ei_raw, int n_idx) {
    int j = blockIdx.x * blockDim.x + threadIdx.x;
    if (j >= n_idx) return;
    long long v;
    if (g_is64) v = ((const long long*)ei_raw)[j];
    else        v = (long long)((const int*)ei_raw)[j];
    if (v < 0) v = 0;
    if (v >= NNODES) v = NNODES - 1;
    g_ei[j] = (int)v;
}

// ---------------- graph setup --------------------------------------------
__global__ void k_zero_deg() {
    int i = blockIdx.x * blockDim.x + threadIdx.x;
    if (i < NNODES) g_deg[i] = 0;
}

__global__ void k_deg(int E) {
    int e = blockIdx.x * blockDim.x + threadIdx.x;
    if (e < E) atomicAdd(&g_deg[g_ei[e]], 1);
}

__global__ void k_dis() {
    int i = blockIdx.x * blockDim.x + threadIdx.x;
    if (i < NNODES) {
        int d = g_deg[i];
        g_dis[i] = (d > 0) ? rsqrtf((float)d) : 0.f;
    }
}

__global__ void k_scan() {
    const int CH = 157;
    __shared__ int s[1024];
    int t = threadIdx.x;
    int base = t * CH;
    int sum = 0;
    for (int j = 0; j < CH; j++) {
        int i = base + j;
        if (i < NNODES) sum += g_deg[i];
    }
    s[t] = sum;
    __syncthreads();
    for (int off = 1; off < 1024; off <<= 1) {
        int v = (t >= off) ? s[t - off] : 0;
        __syncthreads();
        s[t] += v;
        __syncthreads();
    }
    int run = (t > 0) ? s[t - 1] : 0;
    for (int j = 0; j < CH; j++) {
        int i = base + j;
        if (i < NNODES) {
            g_rowptr[i] = run;
            g_fill[i] = run;
            run += g_deg[i];
        }
    }
    if (t == 1023) g_rowptr[NNODES] = s[1023];
}

__global__ void k_fill(int E) {
    int e = blockIdx.x * blockDim.x + threadIdx.x;
    if (e < E) {
        int r = g_ei[e];
        int c = g_ei[E + e];
        int pos = atomicAdd(&g_fill[r], 1);
        if (pos >= 0 && pos < NEDGES)
            g_cw[pos] = make_int2(c, __float_as_int(-g_dis[r] * g_dis[c]));
    }
}

__global__ void k_copy_x(const float* __restrict__ x) {
    int i = blockIdx.x * blockDim.x + threadIdx.x;
    if (i < NNODES) {
        float4 v = make_float4(x[3 * i], x[3 * i + 1], x[3 * i + 2], 0.f);
        *(float4*)&g_tx0p[i * 24] = v;
    }
}

// ---------------- layer0 Chebyshev prop: edge-parallel warp-per-node --------
__global__ void __launch_bounds__(256) k_prop0w(int src_off, int dst_off,
                                                int p_off, int cheb) {
    int warp = (blockIdx.x * blockDim.x + threadIdx.x) >> 5;
    int lane = threadIdx.x & 31;
    if (warp >= NNODES) return;
    int i = warp;
    int s = g_rowptr[i], e = g_rowptr[i + 1];
    float a0 = 0.f, a1 = 0.f, a2 = 0.f;
    for (int j = s + lane; j < e; j += 32) {
        int2 cw = g_cw[j];
        float w = __int_as_float(cw.y);
        float4 v = *(const float4*)&g_tx0p[(size_t)cw.x * 24 + src_off];
        a0 += w * v.x;
        a1 += w * v.y;
        a2 += w * v.z;
    }
    __syncwarp();
#pragma unroll
    for (int off = 16; off > 0; off >>= 1) {
        a0 += __shfl_xor_sync(0xffffffffu, a0, off);
        a1 += __shfl_xor_sync(0xffffffffu, a1, off);
        a2 += __shfl_xor_sync(0xffffffffu, a2, off);
    }
    if (lane == 0) {
        float4 o;
        if (cheb) {
            float4 pv = *(const float4*)&g_tx0p[(size_t)i * 24 + p_off];
            o = make_float4(2.f * a0 - pv.x, 2.f * a1 - pv.y, 2.f * a2 - pv.z, 0.f);
        } else {
            o = make_float4(a0, a1, a2, 0.f);
        }
        *(float4*)&g_tx0p[(size_t)i * 24 + dst_off] = o;
    }
}

// ---------------- layer0 GEMM (padded K=24) + bias + GN + ReLU --------------
__global__ void __launch_bounds__(256) k_gemm_gn0(
    const float* __restrict__ W0, const float* __restrict__ bias,
    const float* __restrict__ gamma, const float* __restrict__ beta) {
    constexpr int BM = 64, KD = 24, COUT = 128;
    constexpr int GS = COUT / GG;

    __shared__ union {
        struct {
            float As[KD][BM + 4];
            float Bs[KD][COUT];
        } ab;
        float Cs[BM][COUT];
    } u;
    __shared__ float mu_s[BM][GG];
    __shared__ float rs_s[BM][GG];

    int tid = threadIdx.x;
    int tx = tid & 15, ty = tid >> 4;
    int row0 = blockIdx.x * BM;

    for (int f = tid; f < BM * KD / 4; f += 256) {
        int r = f / 6, c4 = f % 6;
        float4 v = *(const float4*)&g_tx0p[(size_t)(row0 + r) * KD + c4 * 4];
        u.ab.As[c4 * 4 + 0][r] = v.x;
        u.ab.As[c4 * 4 + 1][r] = v.y;
        u.ab.As[c4 * 4 + 2][r] = v.z;
        u.ab.As[c4 * 4 + 3][r] = v.w;
    }
    for (int f = tid; f < KD * COUT; f += 256) {
        int r = f >> 7, c = f & 127;
        int slice = r >> 2, cc = r & 3;
        u.ab.Bs[r][c] = (cc < 3) ? W0[(slice * 3 + cc) * COUT + c] : 0.f;
    }
    __syncthreads();

    float acc[4][8];
#pragma unroll
    for (int m = 0; m < 4; m++)
#pragma unroll
        for (int n = 0; n < 8; n++) acc[m][n] = 0.f;

#pragma unroll
    for (int kk = 0; kk < KD; kk++) {
        float a[4], b[8];
        *(float4*)&a[0] = *(const float4*)&u.ab.As[kk][ty * 4];
        *(float4*)&b[0] = *(const float4*)&u.ab.Bs[kk][tx * 8];
        *(float4*)&b[4] = *(const float4*)&u.ab.Bs[kk][tx * 8 + 4];
#pragma unroll
        for (int m = 0; m < 4; m++)
#pragma unroll
            for (int n = 0; n < 8; n++) acc[m][n] += a[m] * b[n];
    }
    __syncthreads();

#pragma unroll
    for (int m = 0; m < 4; m++)
#pragma unroll
        for (int n = 0; n < 8; n++)
            u.Cs[ty * 4 + m][tx * 8 + n] = acc[m][n] + bias[tx * 8 + n];
    __syncthreads();

    for (int p = tid; p < BM * GG; p += 256) {
        int r = p / GG, g = p % GG;
        float su = 0.f, sq = 0.f;
#pragma unroll
        for (int c = 0; c < GS; c++) {
            float v = u.Cs[r][g * GS + c];
            su += v;
            sq += v * v;
        }
        float mu = su / GS;
        float var = sq / GS - mu * mu;
        mu_s[r][g] = mu;
        rs_s[r][g] = rsqrtf(var + EPSV);
    }
    __syncthreads();

    for (int p = tid; p < BM * COUT; p += 256) {
        int r = p / COUT, c = p % COUT;
        int g = c / GS;
        float v = (u.Cs[r][c] - mu_s[r][g]) * rs_s[r][g] * gamma[c] + beta[c];
        g_h1[(size_t)(row0 + r) * COUT + c] = fmaxf(v, 0.f);
    }
}

// ---------------- pre-split A (activations) into bf16 hi/lo planes ----------
template <int KDIM, int ABUF>
__global__ void __launch_bounds__(256) k_split_a() {
    constexpr int KP = KDIM / 2;
    const float* A = buf<ABUF>();
    int idx = blockIdx.x * blockDim.x + threadIdx.x;
    if (idx >= NNODES * KP) return;
    int row = idx / KP, kp = idx - row * KP;
    float2 v = *(const float2*)&A[(size_t)row * KDIM + 2 * kp];
    uint32_t hi, lo;
    split_pack(v.x, v.y, hi, lo);
    g_ah[(size_t)row * KP + kp] = hi;
    g_al[(size_t)row * KP + kp] = lo;
}

// ---------------- pre-split W into bf16 hi/lo planes ------------------------
template <int KDIM, int COUT>
__global__ void __launch_bounds__(256) k_split_w(const float* __restrict__ Wt) {
    constexpr int KP = KDIM / 2;
    int idx = blockIdx.x * blockDim.x + threadIdx.x;
    if (idx >= 6 * KP * COUT) return;
    int s = idx / (KP * COUT);
    int rem = idx - s * (KP * COUT);
    int kp = rem / COUT, c = rem - kp * COUT;
    float v0 = Wt[((size_t)s * KDIM + 2 * kp) * COUT + c];
    float v1 = Wt[((size_t)s * KDIM + 2 * kp + 1) * COUT + c];
    uint32_t hi, lo;
    split_pack(v0, v1, hi, lo);
    g_wh[idx] = hi;
    g_wl[idx] = lo;
}

// ---------------- Clenshaw step (COUT=64): warp-per-node --------------------
template <bool FINAL>
__global__ void __launch_bounds__(256) k_clen64(
    int csel, int coff, int cstr,
    int gsel, int goff, int gstr,
    int psel, int poff, int pstr, int use_p,
    int dsel, float coef,
    const float* __restrict__ bias, const float* __restrict__ gamma,
    const float* __restrict__ beta) {
    constexpr int COUT = 64;
    const float* C = bufsel(csel);
    const float* G = bufsel(gsel);
    const float* P = bufsel(psel);
    float* D = bufsel(dsel);

    int warp = (blockIdx.x * blockDim.x + threadIdx.x) >> 5;
    int lane = threadIdx.x & 31;
    if (warp >= NNODES) return;
    int i = warp;
    int s = g_rowptr[i], e = g_rowptr[i + 1];
    int ch = lane * 2;

    float acc0 = 0.f, acc1 = 0.f;
    for (int j0 = s; j0 < e; j0 += 32) {
        int jj = j0 + lane;
        int2 cwv = (jj < e) ? g_cw[jj] : make_int2(0, 0);
        int cc = cwv.x;
        float ww = __int_as_float(cwv.y);
        int cnt = e - j0;
        if (cnt > 32) cnt = 32;
        int t = 0;
        for (; t + 4 <= cnt; t += 4) {
            int c0 = __shfl_sync(0xffffffffu, cc, t);
            int c1 = __shfl_sync(0xffffffffu, cc, t + 1);
            int c2 = __shfl_sync(0xffffffffu, cc, t + 2);
            int c3 = __shfl_sync(0xffffffffu, cc, t + 3);
            float w0 = __shfl_sync(0xffffffffu, ww, t);
            float w1 = __shfl_sync(0xffffffffu, ww, t + 1);
            float w2 = __shfl_sync(0xffffffffu, ww, t + 2);
            float w3 = __shfl_sync(0xffffffffu, ww, t + 3);
            float2 v0 = *(const float2*)&G[(size_t)c0 * gstr + goff + ch];
            float2 v1 = *(const float2*)&G[(size_t)c1 * gstr + goff + ch];
            float2 v2 = *(const float2*)&G[(size_t)c2 * gstr + goff + ch];
            float2 v3 = *(const float2*)&G[(size_t)c3 * gstr + goff + ch];
            acc0 += w0 * v0.x + w1 * v1.x + w2 * v2.x + w3 * v3.x;
            acc1 += w0 * v0.y + w1 * v1.y + w2 * v2.y + w3 * v3.y;
        }
        for (; t < cnt; t++) {
            int c = __shfl_sync(0xffffffffu, cc, t);
            float w = __shfl_sync(0xffffffffu, ww, t);
            float2 v = *(const float2*)&G[(size_t)c * gstr + goff + ch];
            acc0 += w * v.x;
            acc1 += w * v.y;
        }
    }

    float2 cv = *(const float2*)&C[(size_t)i * cstr + coff + ch];
    float v0 = cv.x + coef * acc0;
    float v1 = cv.y + coef * acc1;
    if (use_p) {
        float2 pv = *(const float2*)&P[(size_t)i * pstr + poff + ch];
        v0 -= pv.x;
        v1 -= pv.y;
    }

    if constexpr (FINAL) {
        v0 += bias[ch];
        v1 += bias[ch + 1];
        float su = v0 + v1, sq = v0 * v0 + v1 * v1;
        su += __shfl_xor_sync(0xffffffffu, su, 1);
        su += __shfl_xor_sync(0xffffffffu, su, 2);
        sq += __shfl_xor_sync(0xffffffffu, sq, 1);
        sq += __shfl_xor_sync(0xffffffffu, sq, 2);
        float mu = su * 0.125f;
        float var = sq * 0.125f - mu * mu;
        float rs = rsqrtf(var + EPSV);
        v0 = fmaxf((v0 - mu) * rs * gamma[ch] + beta[ch], 0.f);
        v1 = fmaxf((v1 - mu) * rs * gamma[ch + 1] + beta[ch + 1], 0.f);
    }

    *(float2*)&D[(size_t)i * COUT + ch] = make_float2(v0, v1);
}

// ---------------- Clenshaw step (COUT=32): half-warp-per-node ---------------
template <bool FINAL>
__global__ void __launch_bounds__(256) k_clen32(
    int csel, int coff, int cstr,
    int gsel, int goff, int gstr,
    int psel, int poff, int pstr, int use_p,
    int dsel, float coef,
    const float* __restrict__ bias, const float* __restrict__ gamma,
    const float* __restrict__ beta) {
    constexpr int COUT = 32;
    const float* C = bufsel(csel);
    const float* G = bufsel(gsel);
    const float* P = bufsel(psel);
    float* D = bufsel(dsel);

    int warp = (blockIdx.x * blockDim.x + threadIdx.x) >> 5;
    int lane = threadIdx.x & 31;
    int half = lane >> 4, hl = lane & 15;
    unsigned hmask = half ? 0xFFFF0000u : 0x0000FFFFu;
    int i = warp * 2 + half;
    if (i >= NNODES) return;
    int s = g_rowptr[i], e = g_rowptr[i + 1];
    int ch = hl * 2;

    float acc0 = 0.f, acc1 = 0.f;
    for (int j0 = s; j0 < e; j0 += 16) {
        int jj = j0 + hl;
        int2 cwv = (jj < e) ? g_cw[jj] : make_int2(0, 0);
        int cc = cwv.x;
        float ww = __int_as_float(cwv.y);
        int cnt = e - j0;
        if (cnt > 16) cnt = 16;
        int t = 0;
        for (; t + 4 <= cnt; t += 4) {
            int c0 = __shfl_sync(hmask, cc, t, 16);
            int c1 = __shfl_sync(hmask, cc, t + 1, 16);
            int c2 = __shfl_sync(hmask, cc, t + 2, 16);
            int c3 = __shfl_sync(hmask, cc, t + 3, 16);
            float w0 = __shfl_sync(hmask, ww, t, 16);
            float w1 = __shfl_sync(hmask, ww, t + 1, 16);
            float w2 = __shfl_sync(hmask, ww, t + 2, 16);
            float w3 = __shfl_sync(hmask, ww, t + 3, 16);
            float2 v0 = *(const float2*)&G[(size_t)c0 * gstr + goff + ch];
            float2 v1 = *(const float2*)&G[(size_t)c1 * gstr + goff + ch];
            float2 v2 = *(const float2*)&G[(size_t)c2 * gstr + goff + ch];
            float2 v3 = *(const float2*)&G[(size_t)c3 * gstr + goff + ch];
            acc0 += w0 * v0.x + w1 * v1.x + w2 * v2.x + w3 * v3.x;
            acc1 += w0 * v0.y + w1 * v1.y + w2 * v2.y + w3 * v3.y;
        }
        for (; t < cnt; t++) {
            int c = __shfl_sync(hmask, cc, t, 16);
            float w = __shfl_sync(hmask, ww, t, 16);
            float2 v = *(const float2*)&G[(size_t)c * gstr + goff + ch];
            acc0 += w * v.x;
            acc1 += w * v.y;
        }
    }

    float2 cv = *(const float2*)&C[(size_t)i * cstr + coff + ch];
    float v0 = cv.x + coef * acc0;
    float v1 = cv.y + coef * acc1;
    if (use_p) {
        float2 pv = *(const float2*)&P[(size_t)i * pstr + poff + ch];
        v0 -= pv.x;
        v1 -= pv.y;
    }

    if constexpr (FINAL) {
        v0 += bias[ch];
        v1 += bias[ch + 1];
        __syncwarp();
        float su = v0 + v1, sq = v0 * v0 + v1 * v1;
        su += __shfl_xor_sync(0xffffffffu, su, 1);
        sq += __shfl_xor_sync(0xffffffffu, sq, 1);
        float mu = su * 0.25f;
        float var = sq * 0.25f - mu * mu;
        float rs = rsqrtf(var + EPSV);
        v0 = fmaxf((v0 - mu) * rs * gamma[ch] + beta[ch], 0.f);
        v1 = fmaxf((v1 - mu) * rs * gamma[ch + 1] + beta[ch + 1], 0.f);
    }

    *(float2*)&D[(size_t)i * COUT + ch] = make_float2(v0, v1);
}

// ---------------- HW GEMM (pre-split bf16x3): hw = H @ W[k], 2 slices/block -
// Inner loop is pure LDS + MMA; all float->bf16 splitting hoisted to pre-pass.
template <int KDIM, int COUT>
__global__ void __launch_bounds__(256, 2) k_gemm_hw(int dummy) {
    constexpr int BM = 128, BK = 32;
    constexpr int NT = COUT / 8;
    constexpr int KPT = BK / 2;            // packed pairs per tile (16)
    constexpr int KPF = KDIM / 2;          // packed pairs full K
    constexpr int ASTR = KPT + 4;          // 20: (20*grp+thr4) mod 32 bijective
    constexpr int BSTR = COUT + 8;
    constexpr int CSTR = 6 * COUT;
    float* out = g_hw;
    int ks0 = blockIdx.y * 2;

    __shared__ uint32_t Ah[BM][ASTR];
    __shared__ uint32_t Al[BM][ASTR];
    __shared__ uint32_t Bh[2][KPT][BSTR];
    __shared__ uint32_t Bl[2][KPT][BSTR];

    int tid = threadIdx.x, wid = tid >> 5, lane = tid & 31;
    int grp = lane >> 2, thr4 = lane & 3;
    int row0 = blockIdx.x * BM;

    float acc[2][NT][4];
#pragma unroll
    for (int sl = 0; sl < 2; sl++)
#pragma unroll
        for (int n = 0; n < NT; n++)
#pragma unroll
            for (int q = 0; q < 4; q++) acc[sl][n][q] = 0.f;

    for (int k0 = 0; k0 < KDIM; k0 += BK) {
        int kp0 = k0 / 2;
        // stage A hi/lo: BM x KPT uint32 each, via uint4
#pragma unroll
        for (int f = tid; f < BM * KPT / 4; f += 256) {
            int r = f >> 2, c4 = f & 3;
            uint4 vh = *(const uint4*)&g_ah[(size_t)(row0 + r) * KPF + kp0 + c4 * 4];
            Ah[r][c4 * 4 + 0] = vh.x;
            Ah[r][c4 * 4 + 1] = vh.y;
            Ah[r][c4 * 4 + 2] = vh.z;
            Ah[r][c4 * 4 + 3] = vh.w;
            uint4 vl = *(const uint4*)&g_al[(size_t)(row0 + r) * KPF + kp0 + c4 * 4];
            Al[r][c4 * 4 + 0] = vl.x;
            Al[r][c4 * 4 + 1] = vl.y;
            Al[r][c4 * 4 + 2] = vl.z;
            Al[r][c4 * 4 + 3] = vl.w;
        }
        // stage B hi/lo: direct copy from pre-split tables
#pragma unroll
        for (int sl = 0; sl < 2; sl++) {
#pragma unroll
            for (int f = tid; f < KPT * COUT; f += 256) {
                int kp = f / COUT, c = f % COUT;
                size_t base = ((size_t)(ks0 + sl) * KPF + kp0 + kp) * COUT + c;
                Bh[sl][kp][c] = g_wh[base];
                Bl[sl][kp][c] = g_wl[base];
            }
        }
        __syncthreads();
#pragma unroll
        for (int kk = 0; kk < BK; kk += 16) {
            int kbase = kk >> 1;               // 0 or 8
            int row_g = wid * 16 + grp, row_g8 = row_g + 8;
            uint32_t ah[4], al[4];
            ah[0] = Ah[row_g][kbase + thr4];
            ah[1] = Ah[row_g8][kbase + thr4];
            ah[2] = Ah[row_g][kbase + 4 + thr4];
            ah[3] = Ah[row_g8][kbase + 4 + thr4];
            al[0] = Al[row_g][kbase + thr4];
            al[1] = Al[row_g8][kbase + thr4];
            al[2] = Al[row_g][kbase + 4 + thr4];
            al[3] = Al[row_g8][kbase + 4 + thr4];
            int kp0_ = kbase + thr4, kp1_ = kbase + 4 + thr4;
#pragma unroll
            for (int sl = 0; sl < 2; sl++) {
#pragma unroll
                for (int n = 0; n < NT; n++) {
                    int cb = n * 8 + grp;
                    uint32_t bh0 = Bh[sl][kp0_][cb];
                    uint32_t bh1 = Bh[sl][kp1_][cb];
                    uint32_t bl0 = Bl[sl][kp0_][cb];
                    uint32_t bl1 = Bl[sl][kp1_][cb];
                    asm volatile(
                        "mma.sync.aligned.m16n8k16.row.col.f32.bf16.bf16.f32 "
                        "{%0,%1,%2,%3},{%4,%5,%6,%7},{%8,%9},{%0,%1,%2,%3};"
                        : "+f"(acc[sl][n][0]), "+f"(acc[sl][n][1]), "+f"(acc[sl][n][2]), "+f"(acc[sl][n][3])
                        : "r"(ah[0]), "r"(ah[1]), "r"(ah[2]), "r"(ah[3]), "r"(bh0), "r"(bh1));
                    asm volatile(
                        "mma.sync.aligned.m16n8k16.row.col.f32.bf16.bf16.f32 "
                        "{%0,%1,%2,%3},{%4,%5,%6,%7},{%8,%9},{%0,%1,%2,%3};"
                        : "+f"(acc[sl][n][0]), "+f"(acc[sl][n][1]), "+f"(acc[sl][n][2]), "+f"(acc[sl][n][3])
                        : "r"(al[0]), "r"(al[1]), "r"(al[2]), "r"(al[3]), "r"(bh0), "r"(bh1));
                    asm volatile(
                        "mma.sync.aligned.m16n8k16.row.col.f32.bf16.bf16.f32 "
                        "{%0,%1,%2,%3},{%4,%5,%6,%7},{%8,%9},{%0,%1,%2,%3};"
                        : "+f"(acc[sl][n][0]), "+f"(acc[sl][n][1]), "+f"(acc[sl][n][2]), "+f"(acc[sl][n][3])
                        : "r"(ah[0]), "r"(ah[1]), "r"(ah[2]), "r"(ah[3]), "r"(bl0), "r"(bl1));
                }
            }
        }
        __syncthreads();
    }

    int r0 = wid * 16 + grp;
#pragma unroll
    for (int sl = 0; sl < 2; sl++)
#pragma unroll
        for (int n = 0; n < NT; n++) {
            int cb = n * 8 + thr4 * 2;
            *(float2*)&out[(size_t)(row0 + r0) * CSTR + (ks0 + sl) * COUT + cb] =
                make_float2(acc[sl][n][0], acc[sl][n][1]);
            *(float2*)&out[(size_t)(row0 + r0 + 8) * CSTR + (ks0 + sl) * COUT + cb] =
                make_float2(acc[sl][n][2], acc[sl][n][3]);
        }
}

// ---------------- final dense head: [16,320000]@[320000,128] ----------------
__global__ void __launch_bounds__(256) k_final(const float* __restrict__ W) {
    __shared__ float Hs[16][257];
    int tid = threadIdx.x;
    int o = tid & 127, half = tid >> 7;
    float acc[8];
#pragma unroll
    for (int j = 0; j < 8; j++) acc[j] = 0.f;
    int kbase = blockIdx.x * 512;
    const float* H = g_h3;
    for (int s = 0; s < 2; s++) {
        int k0 = kbase + s * 256;
#pragma unroll
        for (int l = 0; l < 16; l++) {
            int idx = tid + l * 256;
            int b = idx >> 8, kk = idx & 255;
            Hs[b][kk] = H[(size_t)b * 320000 + k0 + kk];
        }
        __syncthreads();
        for (int kk = 0; kk < 256; kk++) {
            float w = W[(size_t)(k0 + kk) * 128 + o];
#pragma unroll
            for (int j = 0; j < 8; j++) acc[j] += Hs[half * 8 + j][kk] * w;
        }
        __syncthreads();
    }
#pragma unroll
    for (int j = 0; j < 8; j++)
        g_partial[(size_t)blockIdx.x * 2048 + (half * 8 + j) * 128 + o] = acc[j];
}

__global__ void k_reduce(const float* __restrict__ blast, float* __restrict__ out) {
    int j = blockIdx.x * blockDim.x + threadIdx.x;
    if (j < 2048) {
        float s = blast[j & 127];
        for (int c = 0; c < 625; c++) s += g_partial[c * 2048 + j];
        out[j] = s;
    }
}

// ---------------- host launcher ---------------------------------------------
extern "C" void kernel_launch(void* const* d_in, const int* in_sizes, int n_in,
                              void* d_out, int out_size) {
    const float* x = (const float*)d_in[0];
    const void* ei = d_in[1];
    const float* W0 = (const float*)d_in[2];
    const float* b0 = (const float*)d_in[3];
    const float* ga0 = (const float*)d_in[4];
    const float* be0 = (const float*)d_in[5];
    const float* W1 = (const float*)d_in[6];
    const float* b1 = (const float*)d_in[7];
    const float* ga1 = (const float*)d_in[8];
    const float* be1 = (const float*)d_in[9];
    const float* W2 = (const float*)d_in[10];
    const float* b2 = (const float*)d_in[11];
    const float* ga2 = (const float*)d_in[12];
    const float* be2 = (const float*)d_in[13];
    const float* Wl = (const float*)d_in[14];
    const float* bl = (const float*)d_in[15];
    float* out = (float*)d_out;

    int n_idx = in_sizes[1];
    int E = n_idx / 2;
    if (E > NEDGES) E = NEDGES;

    k_detect<<<1, 256>>>(ei, n_idx);
    k_convert<<<(n_idx + 255) / 256, 256>>>(ei, n_idx);

    k_zero_deg<<<(NNODES + 255) / 256, 256>>>();
    k_deg<<<(E + 255) / 256, 256>>>(E);
    k_dis<<<(NNODES + 255) / 256, 256>>>();
    k_scan<<<1, 1024>>>();
    k_fill<<<(E + 255) / 256, 256>>>(E);
    k_copy_x<<<(NNODES + 255) / 256, 256>>>(x);

    const int WGRID = (NNODES * 32 + 255) / 256;    // warp-per-node
    const int WGRID2 = (NNODES * 16 + 255) / 256;   // half-warp-per-node
    const int HW = 2, B0 = 3, B1 = 4, B2 = 5, H2 = 6, H3 = 7;

    // ---- layer 0: edge-parallel forward recursion + GEMM 24->128 + GN ------
    for (int k = 1; k < 6; k++)
        k_prop0w<<<WGRID, 256>>>((k - 1) * 4, k * 4,
                                 (k >= 2) ? (k - 2) * 4 : 0, (k >= 2) ? 1 : 0);
    k_gemm_gn0<<<NNODES / 64, 256>>>(W0, b0, ga0, be0);

    // ---- layer 1 (Clenshaw): H1[N,128] -> H2[N,64] --------------------------
    {
        k_split_a<128, 1><<<(NNODES * 64 + 255) / 256, 256>>>();
        k_split_w<128, 64><<<(6 * 64 * 64 + 255) / 256, 256>>>(W1);
        k_gemm_hw<128, 64><<<dim3(NNODES / 128, 3), 256>>>(0);
        k_clen64<false><<<WGRID, 256>>>(HW, 4 * 64, 384, HW, 5 * 64, 384,
                                        0, 0, 0, 0, B0, 2.f, b1, ga1, be1);
        k_clen64<false><<<WGRID, 256>>>(HW, 3 * 64, 384, B0, 0, 64,
                                        HW, 5 * 64, 384, 1, B1, 2.f, b1, ga1, be1);
        k_clen64<false><<<WGRID, 256>>>(HW, 2 * 64, 384, B1, 0, 64,
                                        B0, 0, 64, 1, B2, 2.f, b1, ga1, be1);
        k_clen64<false><<<WGRID, 256>>>(HW, 1 * 64, 384, B2, 0, 64,
                                        B1, 0, 64, 1, B0, 2.f, b1, ga1, be1);
        k_clen64<true><<<WGRID, 256>>>(HW, 0, 384, B0, 0, 64,
                                       B2, 0, 64, 1, H2, 1.f, b1, ga1, be1);
    }

    // ---- layer 2 (Clenshaw): H2[N,64] -> H3[N,32] ---------------------------
    {
        k_split_a<64, 6><<<(NNODES * 32 + 255) / 256, 256>>>();
        k_split_w<64, 32><<<(6 * 32 * 32 + 255) / 256, 256>>>(W2);
        k_gemm_hw<64, 32><<<dim3(NNODES / 128, 3), 256>>>(0);
        k_clen32<false><<<WGRID2, 256>>>(HW, 4 * 32, 192, HW, 5 * 32, 192,
                                         0, 0, 0, 0, B0, 2.f, b2, ga2, be2);
        k_clen32<false><<<WGRID2, 256>>>(HW, 3 * 32, 192, B0, 0, 32,
                                         HW, 5 * 32, 192, 1, B1, 2.f, b2, ga2, be2);
        k_clen32<false><<<WGRID2, 256>>>(HW, 2 * 32, 192, B1, 0, 32,
                                         B0, 0, 32, 1, B2, 2.f, b2, ga2, be2);
        k_clen32<false><<<WGRID2, 256>>>(HW, 1 * 32, 192, B2, 0, 32,
                                         B1, 0, 32, 1, B0, 2.f, b2, ga2, be2);
        k_clen32<true><<<WGRID2, 256>>>(HW, 0, 192, B0, 0, 32,
                                        B2, 0, 32, 1, H3, 1.f, b2, ga2, be2);
    }

    // ---- final dense head ----
    k_final<<<625, 256>>>(Wl);
    k_reduce<<<8, 256>>>(bl, out);
}

// round 17
// speedup vs baseline: 1.1397x; 1.1397x over previous
#include <cuda_runtime.h>
#include <cuda_bf16.h>
#include <cuda_fp16.h>
#include <math.h>
#include <stdint.h>

#define NNODES 160000
#define NEDGES 2560000
#define GG 8
#define EPSV 1e-5f

// ---------------- scratch (device globals; no allocation allowed) ----------
__device__ int   g_is64;
__device__ int   g_ei[2 * NEDGES];
__device__ int   g_deg[NNODES];
__device__ float g_dis[NNODES];
__device__ int   g_rowptr[NNODES + 1];
__device__ int   g_fill[NNODES];
__device__ __align__(16) int2 g_cw[NEDGES];                     // packed (col, w)

__device__ __align__(16) float  g_tx0p[NNODES * 24];            // layer0 Tx padded [N][6][4]
__device__ __align__(16) float  g_h1[(size_t)NNODES * 128];     // layer1 input (fp32)
__device__ __align__(16) __half g_hw[(size_t)NNODES * 384];     // H@W products, fp16 (6 slices)
__device__ __align__(16) __half g_b0[(size_t)NNODES * 64];      // Clenshaw b, fp16
__device__ __align__(16) __half g_b1[(size_t)NNODES * 64];
__device__ __align__(16) __half g_b2[(size_t)NNODES * 64];
__device__ __align__(16) float  g_h2[(size_t)NNODES * 64];      // layer2 input (fp32)
__device__ __align__(16) float  g_h3[NNODES * 32];              // head input (fp32)
__device__ float g_partial[625 * 2048];

__device__ __forceinline__ const __half* halfsel(int b) {
    switch (b) {
        case 2: return g_hw;
        case 3: return g_b0;
        case 4: return g_b1;
        default: return g_b2;
    }
}

__device__ __forceinline__ __half* halfsel_w(int b) {
    switch (b) {
        case 3: return g_b0;
        case 4: return g_b1;
        default: return g_b2;
    }
}

// ---------------- edge dtype detection (parallel) ----------------------------
__global__ void k_detect(const void* ei_raw, int n_elems) {
    __shared__ int bad;
    if (threadIdx.x == 0) bad = 0;
    __syncthreads();
    const long long* p = (const long long*)ei_raw;
    int nw = n_elems / 2;
    if (nw > 2048) nw = 2048;
    for (int j = threadIdx.x; j < nw; j += 256) {
        long long v = p[j];
        if (v < 0 || v >= NNODES) bad = 1;
    }
    __syncthreads();
    if (threadIdx.x == 0) g_is64 = bad ? 0 : 1;
}

__global__ void k_convert(const void* ei_raw, int n_idx) {
    int j = blockIdx.x * blockDim.x + threadIdx.x;
    if (j >= n_idx) return;
    long long v;
    if (g_is64) v = ((const long long*)ei_raw)[j];
    else        v = (long long)((const int*)ei_raw)[j];
    if (v < 0) v = 0;
    if (v >= NNODES) v = NNODES - 1;
    g_ei[j] = (int)v;
}

// ---------------- graph setup --------------------------------------------
__global__ void k_zero_deg() {
    int i = blockIdx.x * blockDim.x + threadIdx.x;
    if (i < NNODES) g_deg[i] = 0;
}

__global__ void k_deg(int E) {
    int e = blockIdx.x * blockDim.x + threadIdx.x;
    if (e < E) atomicAdd(&g_deg[g_ei[e]], 1);
}

__global__ void k_dis() {
    int i = blockIdx.x * blockDim.x + threadIdx.x;
    if (i < NNODES) {
        int d = g_deg[i];
        g_dis[i] = (d > 0) ? rsqrtf((float)d) : 0.f;
    }
}

__global__ void k_scan() {
    const int CH = 157;
    __shared__ int s[1024];
    int t = threadIdx.x;
    int base = t * CH;
    int sum = 0;
    for (int j = 0; j < CH; j++) {
        int i = base + j;
        if (i < NNODES) sum += g_deg[i];
    }
    s[t] = sum;
    __syncthreads();
    for (int off = 1; off < 1024; off <<= 1) {
        int v = (t >= off) ? s[t - off] : 0;
        __syncthreads();
        s[t] += v;
        __syncthreads();
    }
    int run = (t > 0) ? s[t - 1] : 0;
    for (int j = 0; j < CH; j++) {
        int i = base + j;
        if (i < NNODES) {
            g_rowptr[i] = run;
            g_fill[i] = run;
            run += g_deg[i];
        }
    }
    if (t == 1023) g_rowptr[NNODES] = s[1023];
}

__global__ void k_fill(int E) {
    int e = blockIdx.x * blockDim.x + threadIdx.x;
    if (e < E) {
        int r = g_ei[e];
        int c = g_ei[E + e];
        int pos = atomicAdd(&g_fill[r], 1);
        if (pos >= 0 && pos < NEDGES)
            g_cw[pos] = make_int2(c, __float_as_int(-g_dis[r] * g_dis[c]));
    }
}

__global__ void k_copy_x(const float* __restrict__ x) {
    int i = blockIdx.x * blockDim.x + threadIdx.x;
    if (i < NNODES) {
        float4 v = make_float4(x[3 * i], x[3 * i + 1], x[3 * i + 2], 0.f);
        *(float4*)&g_tx0p[i * 24] = v;
    }
}

// ---------------- layer0 Chebyshev prop: edge-parallel warp-per-node --------
__global__ void __launch_bounds__(256) k_prop0w(int src_off, int dst_off,
                                                int p_off, int cheb) {
    int warp = (blockIdx.x * blockDim.x + threadIdx.x) >> 5;
    int lane = threadIdx.x & 31;
    if (warp >= NNODES) return;
    int i = warp;
    int s = g_rowptr[i], e = g_rowptr[i + 1];
    float a0 = 0.f, a1 = 0.f, a2 = 0.f;
    for (int j = s + lane; j < e; j += 32) {
        int2 cw = g_cw[j];
        float w = __int_as_float(cw.y);
        float4 v = *(const float4*)&g_tx0p[(size_t)cw.x * 24 + src_off];
        a0 += w * v.x;
        a1 += w * v.y;
        a2 += w * v.z;
    }
    __syncwarp();
#pragma unroll
    for (int off = 16; off > 0; off >>= 1) {
        a0 += __shfl_xor_sync(0xffffffffu, a0, off);
        a1 += __shfl_xor_sync(0xffffffffu, a1, off);
        a2 += __shfl_xor_sync(0xffffffffu, a2, off);
    }
    if (lane == 0) {
        float4 o;
        if (cheb) {
            float4 pv = *(const float4*)&g_tx0p[(size_t)i * 24 + p_off];
            o = make_float4(2.f * a0 - pv.x, 2.f * a1 - pv.y, 2.f * a2 - pv.z, 0.f);
        } else {
            o = make_float4(a0, a1, a2, 0.f);
        }
        *(float4*)&g_tx0p[(size_t)i * 24 + dst_off] = o;
    }
}

// ---------------- layer0 GEMM (padded K=24) + bias + GN + ReLU --------------
__global__ void __launch_bounds__(256) k_gemm_gn0(
    const float* __restrict__ W0, const float* __restrict__ bias,
    const float* __restrict__ gamma, const float* __restrict__ beta) {
    constexpr int BM = 64, KD = 24, COUT = 128;
    constexpr int GS = COUT / GG;

    __shared__ union {
        struct {
            float As[KD][BM + 4];
            float Bs[KD][COUT];
        } ab;
        float Cs[BM][COUT];
    } u;
    __shared__ float mu_s[BM][GG];
    __shared__ float rs_s[BM][GG];

    int tid = threadIdx.x;
    int tx = tid & 15, ty = tid >> 4;
    int row0 = blockIdx.x * BM;

    for (int f = tid; f < BM * KD / 4; f += 256) {
        int r = f / 6, c4 = f % 6;
        float4 v = *(const float4*)&g_tx0p[(size_t)(row0 + r) * KD + c4 * 4];
        u.ab.As[c4 * 4 + 0][r] = v.x;
        u.ab.As[c4 * 4 + 1][r] = v.y;
        u.ab.As[c4 * 4 + 2][r] = v.z;
        u.ab.As[c4 * 4 + 3][r] = v.w;
    }
    for (int f = tid; f < KD * COUT; f += 256) {
        int r = f >> 7, c = f & 127;
        int slice = r >> 2, cc = r & 3;
        u.ab.Bs[r][c] = (cc < 3) ? W0[(slice * 3 + cc) * COUT + c] : 0.f;
    }
    __syncthreads();

    float acc[4][8];
#pragma unroll
    for (int m = 0; m < 4; m++)
#pragma unroll
        for (int n = 0; n < 8; n++) acc[m][n] = 0.f;

#pragma unroll
    for (int kk = 0; kk < KD; kk++) {
        float a[4], b[8];
        *(float4*)&a[0] = *(const float4*)&u.ab.As[kk][ty * 4];
        *(float4*)&b[0] = *(const float4*)&u.ab.Bs[kk][tx * 8];
        *(float4*)&b[4] = *(const float4*)&u.ab.Bs[kk][tx * 8 + 4];
#pragma unroll
        for (int m = 0; m < 4; m++)
#pragma unroll
            for (int n = 0; n < 8; n++) acc[m][n] += a[m] * b[n];
    }
    __syncthreads();

#pragma unroll
    for (int m = 0; m < 4; m++)
#pragma unroll
        for (int n = 0; n < 8; n++)
            u.Cs[ty * 4 + m][tx * 8 + n] = acc[m][n] + bias[tx * 8 + n];
    __syncthreads();

    for (int p = tid; p < BM * GG; p += 256) {
        int r = p / GG, g = p % GG;
        float su = 0.f, sq = 0.f;
#pragma unroll
        for (int c = 0; c < GS; c++) {
            float v = u.Cs[r][g * GS + c];
            su += v;
            sq += v * v;
        }
        float mu = su / GS;
        float var = sq / GS - mu * mu;
        mu_s[r][g] = mu;
        rs_s[r][g] = rsqrtf(var + EPSV);
    }
    __syncthreads();

    for (int p = tid; p < BM * COUT; p += 256) {
        int r = p / COUT, c = p % COUT;
        int g = c / GS;
        float v = (u.Cs[r][c] - mu_s[r][g]) * rs_s[r][g] * gamma[c] + beta[c];
        g_h1[(size_t)(row0 + r) * COUT + c] = fmaxf(v, 0.f);
    }
}

// ---------------- Clenshaw step (COUT=64): warp-per-node, fp16 buffers ------
template <bool FINAL>
__global__ void __launch_bounds__(256) k_clen64(
    int csel, int coff, int cstr,
    int gsel, int goff, int gstr,
    int psel, int poff, int pstr, int use_p,
    int dsel, float coef,
    const float* __restrict__ bias, const float* __restrict__ gamma,
    const float* __restrict__ beta) {
    constexpr int COUT = 64;
    const __half* C = halfsel(csel);
    const __half* G = halfsel(gsel);
    const __half* P = halfsel(psel);

    int warp = (blockIdx.x * blockDim.x + threadIdx.x) >> 5;
    int lane = threadIdx.x & 31;
    if (warp >= NNODES) return;
    int i = warp;
    int s = g_rowptr[i], e = g_rowptr[i + 1];
    int ch = lane * 2;

    float acc0 = 0.f, acc1 = 0.f;
    for (int j0 = s; j0 < e; j0 += 32) {
        int jj = j0 + lane;
        int2 cwv = (jj < e) ? g_cw[jj] : make_int2(0, 0);
        int cc = cwv.x;
        float ww = __int_as_float(cwv.y);
        int cnt = e - j0;
        if (cnt > 32) cnt = 32;
        int t = 0;
        for (; t + 4 <= cnt; t += 4) {
            int c0 = __shfl_sync(0xffffffffu, cc, t);
            int c1 = __shfl_sync(0xffffffffu, cc, t + 1);
            int c2 = __shfl_sync(0xffffffffu, cc, t + 2);
            int c3 = __shfl_sync(0xffffffffu, cc, t + 3);
            float w0 = __shfl_sync(0xffffffffu, ww, t);
            float w1 = __shfl_sync(0xffffffffu, ww, t + 1);
            float w2 = __shfl_sync(0xffffffffu, ww, t + 2);
            float w3 = __shfl_sync(0xffffffffu, ww, t + 3);
            float2 v0 = __half22float2(*(const __half2*)&G[(size_t)c0 * gstr + goff + ch]);
            float2 v1 = __half22float2(*(const __half2*)&G[(size_t)c1 * gstr + goff + ch]);
            float2 v2 = __half22float2(*(const __half2*)&G[(size_t)c2 * gstr + goff + ch]);
            float2 v3 = __half22float2(*(const __half2*)&G[(size_t)c3 * gstr + goff + ch]);
            acc0 += w0 * v0.x + w1 * v1.x + w2 * v2.x + w3 * v3.x;
            acc1 += w0 * v0.y + w1 * v1.y + w2 * v2.y + w3 * v3.y;
        }
        for (; t < cnt; t++) {
            int c = __shfl_sync(0xffffffffu, cc, t);
            float w = __shfl_sync(0xffffffffu, ww, t);
            float2 v = __half22float2(*(const __half2*)&G[(size_t)c * gstr + goff + ch]);
            acc0 += w * v.x;
            acc1 += w * v.y;
        }
    }

    float2 cv = __half22float2(*(const __half2*)&C[(size_t)i * cstr + coff + ch]);
    float v0 = cv.x + coef * acc0;
    float v1 = cv.y + coef * acc1;
    if (use_p) {
        float2 pv = __half22float2(*(const __half2*)&P[(size_t)i * pstr + poff + ch]);
        v0 -= pv.x;
        v1 -= pv.y;
    }

    if constexpr (FINAL) {
        v0 += bias[ch];
        v1 += bias[ch + 1];
        float su = v0 + v1, sq = v0 * v0 + v1 * v1;
        su += __shfl_xor_sync(0xffffffffu, su, 1);
        su += __shfl_xor_sync(0xffffffffu, su, 2);
        sq += __shfl_xor_sync(0xffffffffu, sq, 1);
        sq += __shfl_xor_sync(0xffffffffu, sq, 2);
        float mu = su * 0.125f;
        float var = sq * 0.125f - mu * mu;
        float rs = rsqrtf(var + EPSV);
        v0 = fmaxf((v0 - mu) * rs * gamma[ch] + beta[ch], 0.f);
        v1 = fmaxf((v1 - mu) * rs * gamma[ch + 1] + beta[ch + 1], 0.f);
        *(float2*)&g_h2[(size_t)i * COUT + ch] = make_float2(v0, v1);
    } else {
        __half* D = halfsel_w(dsel);
        __half2 o = __floats2half2_rn(v0, v1);
        *(__half2*)&D[(size_t)i * COUT + ch] = o;
    }
}

// ---------------- Clenshaw step (COUT=32): half-warp-per-node, fp16 ---------
template <bool FINAL>
__global__ void __launch_bounds__(256) k_clen32(
    int csel, int coff, int cstr,
    int gsel, int goff, int gstr,
    int psel, int poff, int pstr, int use_p,
    int dsel, float coef,
    const float* __restrict__ bias, const float* __restrict__ gamma,
    const float* __restrict__ beta) {
    constexpr int COUT = 32;
    const __half* C = halfsel(csel);
    const __half* G = halfsel(gsel);
    const __half* P = halfsel(psel);

    int warp = (blockIdx.x * blockDim.x + threadIdx.x) >> 5;
    int lane = threadIdx.x & 31;
    int half = lane >> 4, hl = lane & 15;
    unsigned hmask = half ? 0xFFFF0000u : 0x0000FFFFu;
    int i = warp * 2 + half;
    if (i >= NNODES) return;
    int s = g_rowptr[i], e = g_rowptr[i + 1];
    int ch = hl * 2;

    float acc0 = 0.f, acc1 = 0.f;
    for (int j0 = s; j0 < e; j0 += 16) {
        int jj = j0 + hl;
        int2 cwv = (jj < e) ? g_cw[jj] : make_int2(0, 0);
        int cc = cwv.x;
        float ww = __int_as_float(cwv.y);
        int cnt = e - j0;
        if (cnt > 16) cnt = 16;
        int t = 0;
        for (; t + 4 <= cnt; t += 4) {
            int c0 = __shfl_sync(hmask, cc, t, 16);
            int c1 = __shfl_sync(hmask, cc, t + 1, 16);
            int c2 = __shfl_sync(hmask, cc, t + 2, 16);
            int c3 = __shfl_sync(hmask, cc, t + 3, 16);
            float w0 = __shfl_sync(hmask, ww, t, 16);
            float w1 = __shfl_sync(hmask, ww, t + 1, 16);
            float w2 = __shfl_sync(hmask, ww, t + 2, 16);
            float w3 = __shfl_sync(hmask, ww, t + 3, 16);
            float2 v0 = __half22float2(*(const __half2*)&G[(size_t)c0 * gstr + goff + ch]);
            float2 v1 = __half22float2(*(const __half2*)&G[(size_t)c1 * gstr + goff + ch]);
            float2 v2 = __half22float2(*(const __half2*)&G[(size_t)c2 * gstr + goff + ch]);
            float2 v3 = __half22float2(*(const __half2*)&G[(size_t)c3 * gstr + goff + ch]);
            acc0 += w0 * v0.x + w1 * v1.x + w2 * v2.x + w3 * v3.x;
            acc1 += w0 * v0.y + w1 * v1.y + w2 * v2.y + w3 * v3.y;
        }
        for (; t < cnt; t++) {
            int c = __shfl_sync(hmask, cc, t, 16);
            float w = __shfl_sync(hmask, ww, t, 16);
            float2 v = __half22float2(*(const __half2*)&G[(size_t)c * gstr + goff + ch]);
            acc0 += w * v.x;
            acc1 += w * v.y;
        }
    }

    float2 cv = __half22float2(*(const __half2*)&C[(size_t)i * cstr + coff + ch]);
    float v0 = cv.x + coef * acc0;
    float v1 = cv.y + coef * acc1;
    if (use_p) {
        float2 pv = __half22float2(*(const __half2*)&P[(size_t)i * pstr + poff + ch]);
        v0 -= pv.x;
        v1 -= pv.y;
    }

    if constexpr (FINAL) {
        v0 += bias[ch];
        v1 += bias[ch + 1];
        __syncwarp();
        float su = v0 + v1, sq = v0 * v0 + v1 * v1;
        su += __shfl_xor_sync(0xffffffffu, su, 1);
        sq += __shfl_xor_sync(0xffffffffu, sq, 1);
        float mu = su * 0.25f;
        float var = sq * 0.25f - mu * mu;
        float rs = rsqrtf(var + EPSV);
        v0 = fmaxf((v0 - mu) * rs * gamma[ch] + beta[ch], 0.f);
        v1 = fmaxf((v1 - mu) * rs * gamma[ch + 1] + beta[ch + 1], 0.f);
        *(float2*)&g_h3[(size_t)i * COUT + ch] = make_float2(v0, v1);
    } else {
        __half* D = halfsel_w(dsel);
        __half2 o = __floats2half2_rn(v0, v1);
        *(__half2*)&D[(size_t)i * COUT + ch] = o;
    }
}

// ---------------- HW GEMM: hw = H @ W[k], 2 K-slices per block --------------
// bf16x3 compensated (round-14 version: in-loop A split); fp16 output.
template <int KDIM, int COUT, int L1IN>
__global__ void __launch_bounds__(256, 2) k_gemm_hw(const float* __restrict__ Wt) {
    constexpr int BM = 128, BK = 32;
    constexpr int NT = COUT / 8;
    constexpr int ASTR = BK + 4;
    constexpr int BSTR = COUT + 8;
    constexpr int CSTR = 6 * COUT;
    constexpr int KP = BK / 2;
    const float* A = L1IN ? g_h1 : g_h2;
    __half* out = g_hw;
    int ks0 = blockIdx.y * 2;

    __shared__ float As[BM][ASTR];
    __shared__ uint32_t Bh[2][KP][BSTR];
    __shared__ uint32_t Bl[2][KP][BSTR];

    int tid = threadIdx.x, wid = tid >> 5, lane = tid & 31;
    int grp = lane >> 2, thr4 = lane & 3;
    int row0 = blockIdx.x * BM;

    float acc[2][NT][4];
#pragma unroll
    for (int sl = 0; sl < 2; sl++)
#pragma unroll
        for (int n = 0; n < NT; n++)
#pragma unroll
            for (int q = 0; q < 4; q++) acc[sl][n][q] = 0.f;

    for (int k0 = 0; k0 < KDIM; k0 += BK) {
#pragma unroll
        for (int f = tid; f < BM * BK / 4; f += 256) {
            int r = f >> 3, c4 = f & 7;
            float4 v = *(const float4*)&A[(size_t)(row0 + r) * KDIM + k0 + c4 * 4];
            As[r][c4 * 4 + 0] = v.x;
            As[r][c4 * 4 + 1] = v.y;
            As[r][c4 * 4 + 2] = v.z;
            As[r][c4 * 4 + 3] = v.w;
        }
#pragma unroll
        for (int sl = 0; sl < 2; sl++) {
#pragma unroll
            for (int f = tid; f < KP * COUT; f += 256) {
                int kp = f / COUT, c = f % COUT;
                const float* wp = &Wt[((size_t)(ks0 + sl) * KDIM + k0 + 2 * kp) * COUT + c];
                float v0 = wp[0], v1 = wp[COUT];
                __nv_bfloat162 h = __floats2bfloat162_rn(v0, v1);
                float r0 = v0 - __low2float(h);
                float r1 = v1 - __high2float(h);
                __nv_bfloat162 l = __floats2bfloat162_rn(r0, r1);
                Bh[sl][kp][c] = *(uint32_t*)&h;
                Bl[sl][kp][c] = *(uint32_t*)&l;
            }
        }
        __syncthreads();
#pragma unroll
        for (int kk = 0; kk < BK; kk += 16) {
            int row_g = wid * 16 + grp, row_g8 = row_g + 8;
            int kc0 = kk + 2 * thr4, kc1 = kk + 8 + 2 * thr4;
            uint32_t ah[4], al[4];
            {
                const int rows[4] = {row_g, row_g8, row_g, row_g8};
                const int kcs[4] = {kc0, kc0, kc1, kc1};
#pragma unroll
                for (int q = 0; q < 4; q++) {
                    float a0 = As[rows[q]][kcs[q]];
                    float a1 = As[rows[q]][kcs[q] + 1];
                    __nv_bfloat162 h = __floats2bfloat162_rn(a0, a1);
                    float r0 = a0 - __low2float(h);
                    float r1 = a1 - __high2float(h);
                    __nv_bfloat162 l = __floats2bfloat162_rn(r0, r1);
                    ah[q] = *(uint32_t*)&h;
                    al[q] = *(uint32_t*)&l;
                }
            }
            int kp0 = (kk >> 1) + thr4, kp1 = kp0 + 4;
#pragma unroll
            for (int sl = 0; sl < 2; sl++) {
#pragma unroll
                for (int n = 0; n < NT; n++) {
                    int cb = n * 8 + grp;
                    uint32_t bh0 = Bh[sl][kp0][cb];
                    uint32_t bh1 = Bh[sl][kp1][cb];
                    uint32_t bl0 = Bl[sl][kp0][cb];
                    uint32_t bl1 = Bl[sl][kp1][cb];
                    asm volatile(
                        "mma.sync.aligned.m16n8k16.row.col.f32.bf16.bf16.f32 "
                        "{%0,%1,%2,%3},{%4,%5,%6,%7},{%8,%9},{%0,%1,%2,%3};"
                        : "+f"(acc[sl][n][0]), "+f"(acc[sl][n][1]), "+f"(acc[sl][n][2]), "+f"(acc[sl][n][3])
                        : "r"(ah[0]), "r"(ah[1]), "r"(ah[2]), "r"(ah[3]), "r"(bh0), "r"(bh1));
                    asm volatile(
                        "mma.sync.aligned.m16n8k16.row.col.f32.bf16.bf16.f32 "
                        "{%0,%1,%2,%3},{%4,%5,%6,%7},{%8,%9},{%0,%1,%2,%3};"
                        : "+f"(acc[sl][n][0]), "+f"(acc[sl][n][1]), "+f"(acc[sl][n][2]), "+f"(acc[sl][n][3])
                        : "r"(al[0]), "r"(al[1]), "r"(al[2]), "r"(al[3]), "r"(bh0), "r"(bh1));
                    asm volatile(
                        "mma.sync.aligned.m16n8k16.row.col.f32.bf16.bf16.f32 "
                        "{%0,%1,%2,%3},{%4,%5,%6,%7},{%8,%9},{%0,%1,%2,%3};"
                        : "+f"(acc[sl][n][0]), "+f"(acc[sl][n][1]), "+f"(acc[sl][n][2]), "+f"(acc[sl][n][3])
                        : "r"(ah[0]), "r"(ah[1]), "r"(ah[2]), "r"(ah[3]), "r"(bl0), "r"(bl1));
                }
            }
        }
        __syncthreads();
    }

    int r0 = wid * 16 + grp;
#pragma unroll
    for (int sl = 0; sl < 2; sl++)
#pragma unroll
        for (int n = 0; n < NT; n++) {
            int cb = n * 8 + thr4 * 2;
            __half2 p0 = __floats2half2_rn(acc[sl][n][0], acc[sl][n][1]);
            __half2 p1 = __floats2half2_rn(acc[sl][n][2], acc[sl][n][3]);
            *(__half2*)&out[(size_t)(row0 + r0) * CSTR + (ks0 + sl) * COUT + cb] = p0;
            *(__half2*)&out[(size_t)(row0 + r0 + 8) * CSTR + (ks0 + sl) * COUT + cb] = p1;
        }
}

// ---------------- final dense head: [16,320000]@[320000,128] ----------------
__global__ void __launch_bounds__(256) k_final(const float* __restrict__ W) {
    __shared__ float Hs[16][257];
    int tid = threadIdx.x;
    int o = tid & 127, half = tid >> 7;
    float acc[8];
#pragma unroll
    for (int j = 0; j < 8; j++) acc[j] = 0.f;
    int kbase = blockIdx.x * 512;
    const float* H = g_h3;
    for (int s = 0; s < 2; s++) {
        int k0 = kbase + s * 256;
#pragma unroll
        for (int l = 0; l < 16; l++) {
            int idx = tid + l * 256;
            int b = idx >> 8, kk = idx & 255;
            Hs[b][kk] = H[(size_t)b * 320000 + k0 + kk];
        }
        __syncthreads();
        for (int kk = 0; kk < 256; kk++) {
            float w = W[(size_t)(k0 + kk) * 128 + o];
#pragma unroll
            for (int j = 0; j < 8; j++) acc[j] += Hs[half * 8 + j][kk] * w;
        }
        __syncthreads();
    }
#pragma unroll
    for (int j = 0; j < 8; j++)
        g_partial[(size_t)blockIdx.x * 2048 + (half * 8 + j) * 128 + o] = acc[j];
}

__global__ void k_reduce(const float* __restrict__ blast, float* __restrict__ out) {
    int j = blockIdx.x * blockDim.x + threadIdx.x;
    if (j < 2048) {
        float s = blast[j & 127];
        for (int c = 0; c < 625; c++) s += g_partial[c * 2048 + j];
        out[j] = s;
    }
}

// ---------------- host launcher ---------------------------------------------
extern "C" void kernel_launch(void* const* d_in, const int* in_sizes, int n_in,
                              void* d_out, int out_size) {
    const float* x = (const float*)d_in[0];
    const void* ei = d_in[1];
    const float* W0 = (const float*)d_in[2];
    const float* b0 = (const float*)d_in[3];
    const float* ga0 = (const float*)d_in[4];
    const float* be0 = (const float*)d_in[5];
    const float* W1 = (const float*)d_in[6];
    const float* b1 = (const float*)d_in[7];
    const float* ga1 = (const float*)d_in[8];
    const float* be1 = (const float*)d_in[9];
    const float* W2 = (const float*)d_in[10];
    const float* b2 = (const float*)d_in[11];
    const float* ga2 = (const float*)d_in[12];
    const float* be2 = (const float*)d_in[13];
    const float* Wl = (const float*)d_in[14];
    const float* bl = (const float*)d_in[15];
    float* out = (float*)d_out;

    int n_idx = in_sizes[1];
    int E = n_idx / 2;
    if (E > NEDGES) E = NEDGES;

    k_detect<<<1, 256>>>(ei, n_idx);
    k_convert<<<(n_idx + 255) / 256, 256>>>(ei, n_idx);

    k_zero_deg<<<(NNODES + 255) / 256, 256>>>();
    k_deg<<<(E + 255) / 256, 256>>>(E);
    k_dis<<<(NNODES + 255) / 256, 256>>>();
    k_scan<<<1, 1024>>>();
    k_fill<<<(E + 255) / 256, 256>>>(E);
    k_copy_x<<<(NNODES + 255) / 256, 256>>>(x);

    const int WGRID = (NNODES * 32 + 255) / 256;    // warp-per-node
    const int WGRID2 = (NNODES * 16 + 255) / 256;   // half-warp-per-node
    const int HW = 2, B0 = 3, B1 = 4, B2 = 5;

    // ---- layer 0: edge-parallel forward recursion + GEMM 24->128 + GN ------
    for (int k = 1; k < 6; k++)
        k_prop0w<<<WGRID, 256>>>((k - 1) * 4, k * 4,
                                 (k >= 2) ? (k - 2) * 4 : 0, (k >= 2) ? 1 : 0);
    k_gemm_gn0<<<NNODES / 64, 256>>>(W0, b0, ga0, be0);

    // ---- layer 1 (Clenshaw): H1[N,128] -> H2[N,64] --------------------------
    {
        k_gemm_hw<128, 64, 1><<<dim3(NNODES / 128, 3), 256>>>(W1);
        k_clen64<false><<<WGRID, 256>>>(HW, 4 * 64, 384, HW, 5 * 64, 384,
                                        HW, 0, 0, 0, B0, 2.f, b1, ga1, be1);
        k_clen64<false><<<WGRID, 256>>>(HW, 3 * 64, 384, B0, 0, 64,
                                        HW, 5 * 64, 384, 1, B1, 2.f, b1, ga1, be1);
        k_clen64<false><<<WGRID, 256>>>(HW, 2 * 64, 384, B1, 0, 64,
                                        B0, 0, 64, 1, B2, 2.f, b1, ga1, be1);
        k_clen64<false><<<WGRID, 256>>>(HW, 1 * 64, 384, B2, 0, 64,
                                        B1, 0, 64, 1, B0, 2.f, b1, ga1, be1);
        k_clen64<true><<<WGRID, 256>>>(HW, 0, 384, B0, 0, 64,
                                       B2, 0, 64, 1, 0, 1.f, b1, ga1, be1);
    }

    // ---- layer 2 (Clenshaw): H2[N,64] -> H3[N,32] ---------------------------
    {
        k_gemm_hw<64, 32, 0><<<dim3(NNODES / 128, 3), 256>>>(W2);
        k_clen32<false><<<WGRID2, 256>>>(HW, 4 * 32, 192, HW, 5 * 32, 192,
                                         HW, 0, 0, 0, B0, 2.f, b2, ga2, be2);
        k_clen32<false><<<WGRID2, 256>>>(HW, 3 * 32, 192, B0, 0, 32,
                                         HW, 5 * 32, 192, 1, B1, 2.f, b2, ga2, be2);
        k_clen32<false><<<WGRID2, 256>>>(HW, 2 * 32, 192, B1, 0, 32,
                                         B0, 0, 32, 1, B2, 2.f, b2, ga2, be2);
        k_clen32<false><<<WGRID2, 256>>>(HW, 1 * 32, 192, B2, 0, 32,
                                         B1, 0, 32, 1, B0, 2.f, b2, ga2, be2);
        k_clen32<true><<<WGRID2, 256>>>(HW, 0, 192, B0, 0, 32,
                                        B2, 0, 32, 1, 0, 1.f, b2, ga2, be2);
    }

    // ---- final dense head ----
    k_final<<<625, 256>>>(Wl);
    k_reduce<<<8, 256>>>(bl, out);
}